// round 1
// baseline (speedup 1.0000x reference)
#include <cuda_runtime.h>
#include <math.h>

#define NB 131072
#define NH 512
#define NL 256
#define NK 1024
#define NF 267

// ---------------- scratch (device globals: allocation-free) ----------------
__device__ float  g_bufA[(size_t)NB * NH];
__device__ float  g_bufB[(size_t)NB * NH];
__device__ float  g_mu  [(size_t)NB * NL];
__device__ float  g_q   [(size_t)NB * NL];
__device__ float  g_enorm[NK];
__device__ int    g_counts[NK];
__device__ double g_loss;

// ---------------- generic fused GEMM: C = act( [A0|A1] @ W + bias ) --------
// A logical shape [NB, Ktot], A0 width K0, A1 width Ktot-K0 (A1 may be null
// when K0 == Ktot). W is [Ktot, N] row-major. Tile: 128x128x16, 256 threads,
// 8x8 per-thread micro-tile.
template <bool RELU>
__global__ void __launch_bounds__(256, 2) gemm_kernel(
    const float* __restrict__ A0, int K0,
    const float* __restrict__ A1, int Ktot,
    const float* __restrict__ W, const float* __restrict__ bias,
    float* __restrict__ C, int N)
{
    __shared__ float As[128][17];   // [m][k], padded: conflict-free store & read
    __shared__ float Ws[16][128];   // [k][n]

    const int t  = threadIdx.x;
    const int tx = t & 15;
    const int ty = t >> 4;
    const int m0 = blockIdx.x * 128;
    const int n0 = blockIdx.y * 128;
    const int K1 = Ktot - K0;

    float acc[8][8];
#pragma unroll
    for (int i = 0; i < 8; ++i)
#pragma unroll
        for (int j = 0; j < 8; ++j) acc[i][j] = 0.f;

    const int nKt = (Ktot + 15) >> 4;
    for (int kt = 0; kt < nKt; ++kt) {
        // A tile: 2048 elems, 8 per thread, coalesced along k
#pragma unroll
        for (int i = 0; i < 8; ++i) {
            int li = t + i * 256;
            int m = li >> 4, k = li & 15;
            int kg = kt * 16 + k;
            float v = 0.f;
            if (kg < Ktot) {
                size_t row = (size_t)(m0 + m);
                v = (kg < K0) ? A0[row * K0 + kg]
                              : A1[row * K1 + (kg - K0)];
            }
            As[m][k] = v;
        }
        // W tile: coalesced along n
#pragma unroll
        for (int i = 0; i < 8; ++i) {
            int li = t + i * 256;
            int n = li & 127, k = li >> 7;
            int kg = kt * 16 + k;
            int ng = n0 + n;
            float v = 0.f;
            if (kg < Ktot && ng < N) v = W[(size_t)kg * N + ng];
            Ws[k][n] = v;
        }
        __syncthreads();
#pragma unroll
        for (int kk = 0; kk < 16; ++kk) {
            float a[8], b[8];
#pragma unroll
            for (int i = 0; i < 8; ++i) a[i] = As[ty * 8 + i][kk];
            float4 b0 = *(const float4*)&Ws[kk][tx * 8];
            float4 b1 = *(const float4*)&Ws[kk][tx * 8 + 4];
            b[0] = b0.x; b[1] = b0.y; b[2] = b0.z; b[3] = b0.w;
            b[4] = b1.x; b[5] = b1.y; b[6] = b1.z; b[7] = b1.w;
#pragma unroll
            for (int i = 0; i < 8; ++i)
#pragma unroll
                for (int j = 0; j < 8; ++j) acc[i][j] += a[i] * b[j];
        }
        __syncthreads();
    }

    // epilogue: bias + optional relu
    if ((n0 + 128 <= N) && ((N & 3) == 0)) {
#pragma unroll
        for (int i = 0; i < 8; ++i) {
            size_t row = (size_t)(m0 + ty * 8 + i);
            float* cp = &C[row * N + n0 + tx * 8];
            float o[8];
#pragma unroll
            for (int j = 0; j < 8; ++j) {
                float v = acc[i][j] + bias[n0 + tx * 8 + j];
                if (RELU) v = fmaxf(v, 0.f);
                o[j] = v;
            }
            *(float4*)cp       = make_float4(o[0], o[1], o[2], o[3]);
            *(float4*)(cp + 4) = make_float4(o[4], o[5], o[6], o[7]);
        }
    } else {
#pragma unroll
        for (int j = 0; j < 8; ++j) {
            int ng = n0 + tx * 8 + j;
            if (ng >= N) continue;
            float bb = bias[ng];
#pragma unroll
            for (int i = 0; i < 8; ++i) {
                float v = acc[i][j] + bb;
                if (RELU) v = fmaxf(v, 0.f);
                C[(size_t)(m0 + ty * 8 + i) * N + ng] = v;
            }
        }
    }
}

// ---------------- precompute ||e_k||^2 ----------------
__global__ void enorm_kernel(const float* __restrict__ embed)
{
    int k = blockIdx.x * 256 + threadIdx.x;  // 1024 total
    float s = 0.f;
    for (int l = 0; l < NL; ++l) {
        float v = embed[(size_t)l * NK + k];
        s += v * v;
    }
    g_enorm[k] = s;
}

__global__ void zero_kernel()
{
    int t = blockIdx.x * 256 + threadIdx.x;
    if (t < NK) g_counts[t] = 0;
    if (t == 0) g_loss = 0.0;
}

// ---------------- vector quantizer ----------------
// Per 128-row tile: scores[k] = ||e_k||^2 - 2 mu.e_k (row-constant ||mu||^2
// dropped; argmin unchanged). GEMM skeleton, per-row argmin, gather quantize,
// MSE partial sum, code histogram.
__global__ void __launch_bounds__(256) vq_kernel(
    const float* __restrict__ mu, const float* __restrict__ embed,
    float* __restrict__ quant)
{
    __shared__ float As[128][17];
    __shared__ float Es[16][128];
    __shared__ float redv[128][17];
    __shared__ int   redi[128][17];
    __shared__ int   sidx[128];
    __shared__ float rsum[256];

    const int t  = threadIdx.x;
    const int tx = t & 15;
    const int ty = t >> 4;
    const int m0 = blockIdx.x * 128;

    float best[8]; int bidx[8];
#pragma unroll
    for (int i = 0; i < 8; ++i) { best[i] = 3.4e38f; bidx[i] = 0; }

    for (int nt = 0; nt < 8; ++nt) {        // 8 code tiles of 128
        float acc[8][8];
#pragma unroll
        for (int i = 0; i < 8; ++i)
#pragma unroll
            for (int j = 0; j < 8; ++j) acc[i][j] = 0.f;

        for (int kt = 0; kt < 16; ++kt) {   // K = 256
#pragma unroll
            for (int i = 0; i < 8; ++i) {
                int li = t + i * 256;
                int m = li >> 4, k = li & 15;
                As[m][k] = mu[(size_t)(m0 + m) * NL + kt * 16 + k];
            }
#pragma unroll
            for (int i = 0; i < 8; ++i) {
                int li = t + i * 256;
                int n = li & 127, k = li >> 7;
                Es[k][n] = embed[(size_t)(kt * 16 + k) * NK + nt * 128 + n];
            }
            __syncthreads();
#pragma unroll
            for (int kk = 0; kk < 16; ++kk) {
                float a[8], b[8];
#pragma unroll
                for (int i = 0; i < 8; ++i) a[i] = As[ty * 8 + i][kk];
                float4 b0 = *(const float4*)&Es[kk][tx * 8];
                float4 b1 = *(const float4*)&Es[kk][tx * 8 + 4];
                b[0] = b0.x; b[1] = b0.y; b[2] = b0.z; b[3] = b0.w;
                b[4] = b1.x; b[5] = b1.y; b[6] = b1.z; b[7] = b1.w;
#pragma unroll
                for (int i = 0; i < 8; ++i)
#pragma unroll
                    for (int j = 0; j < 8; ++j) acc[i][j] += a[i] * b[j];
            }
            __syncthreads();
        }
#pragma unroll
        for (int j = 0; j < 8; ++j) {
            int code = nt * 128 + tx * 8 + j;
            float en = g_enorm[code];
#pragma unroll
            for (int i = 0; i < 8; ++i) {
                float d = en - 2.f * acc[i][j];
                if (d < best[i] || (d == best[i] && code < bidx[i])) {
                    best[i] = d; bidx[i] = code;
                }
            }
        }
    }

    // cross-thread argmin per row (tie -> smallest code, matches argmax(-d))
#pragma unroll
    for (int i = 0; i < 8; ++i) {
        redv[ty * 8 + i][tx] = best[i];
        redi[ty * 8 + i][tx] = bidx[i];
    }
    __syncthreads();
    if (t < 128) {
        float bv = redv[t][0]; int bi = redi[t][0];
#pragma unroll
        for (int x = 1; x < 16; ++x) {
            float v = redv[t][x]; int ix = redi[t][x];
            if (v < bv || (v == bv && ix < bi)) { bv = v; bi = ix; }
        }
        sidx[t] = bi;
        atomicAdd(&g_counts[bi], 1);
    }
    __syncthreads();

    // gather quantize rows (embed fully L2-resident) + MSE partial
    float ls = 0.f;
    for (int r = 0; r < 128; ++r) {
        int code = sidx[r];
        float qv = embed[(size_t)t * NK + code];          // t = latent dim (0..255)
        float mv = mu[(size_t)(m0 + r) * NL + t];
        quant[(size_t)(m0 + r) * NL + t] = qv;
        float d = qv - mv;
        ls += d * d;
    }
    rsum[t] = ls;
    __syncthreads();
    for (int s = 128; s > 0; s >>= 1) {
        if (t < s) rsum[t] += rsum[t + s];
        __syncthreads();
    }
    if (t == 0) atomicAdd(&g_loss, (double)rsum[0]);
}

// ---------------- loss / perplexity scalars ----------------
__global__ void finalize_kernel(float* __restrict__ out)
{
    __shared__ double sh[256];
    int t = threadIdx.x;
    double e = 0.0;
    for (int k = t; k < NK; k += 256) {
        double p = (double)g_counts[k] / (double)NB;
        e += p * log(p + 1e-10);
    }
    sh[t] = e;
    __syncthreads();
    for (int s = 128; s > 0; s >>= 1) {
        if (t < s) sh[t] += sh[t + s];
        __syncthreads();
    }
    if (t == 0) {
        out[(size_t)NB * NF]     = (float)(g_loss / ((double)NB * (double)NL));
        out[(size_t)NB * NF + 1] = (float)exp(-sh[0]);
    }
}

// ---------------- launch ----------------
extern "C" void kernel_launch(void* const* d_in, const int* in_sizes, int n_in,
                              void* d_out, int out_size)
{
    const float* x     = (const float*)d_in[0];
    const float* c     = (const float*)d_in[1];
    const float* W1    = (const float*)d_in[2];
    const float* b1    = (const float*)d_in[3];
    const float* W2    = (const float*)d_in[4];
    const float* b2    = (const float*)d_in[5];
    const float* W3    = (const float*)d_in[6];
    const float* b3    = (const float*)d_in[7];
    const float* Wmu   = (const float*)d_in[8];
    const float* bmu   = (const float*)d_in[9];
    const float* W4    = (const float*)d_in[10];
    const float* b4    = (const float*)d_in[11];
    const float* W5    = (const float*)d_in[12];
    const float* b5    = (const float*)d_in[13];
    const float* W6    = (const float*)d_in[14];
    const float* b6    = (const float*)d_in[15];
    const float* Wo    = (const float*)d_in[16];
    const float* bo    = (const float*)d_in[17];
    const float* embed = (const float*)d_in[18];
    float* out = (float*)d_out;

    float *bufA, *bufB, *mu, *q;
    cudaGetSymbolAddress((void**)&bufA, g_bufA);
    cudaGetSymbolAddress((void**)&bufB, g_bufB);
    cudaGetSymbolAddress((void**)&mu,   g_mu);
    cudaGetSymbolAddress((void**)&q,    g_q);

    const dim3 blk(256);
    const int MT = NB / 128;  // 1024

    zero_kernel<<<4, blk>>>();
    enorm_kernel<<<4, blk>>>(embed);

    // encoder
    gemm_kernel<true ><<<dim3(MT, 4), blk>>>(x,    NF,  c,      2 * NF, W1,  b1,  bufA, NH);
    gemm_kernel<true ><<<dim3(MT, 4), blk>>>(bufA, NH,  nullptr, NH,    W2,  b2,  bufB, NH);
    gemm_kernel<true ><<<dim3(MT, 4), blk>>>(bufB, NH,  nullptr, NH,    W3,  b3,  bufA, NH);
    gemm_kernel<false><<<dim3(MT, 2), blk>>>(bufA, NH,  nullptr, NH,    Wmu, bmu, mu,   NL);

    // vector quantizer
    vq_kernel<<<MT, blk>>>(mu, embed, q);

    // decoder
    gemm_kernel<true ><<<dim3(MT, 4), blk>>>(q,    NL,  c,      NL + NF, W4, b4, bufA, NH);
    gemm_kernel<true ><<<dim3(MT, 4), blk>>>(bufA, NH,  nullptr, NH,     W5, b5, bufB, NH);
    gemm_kernel<true ><<<dim3(MT, 4), blk>>>(bufB, NH,  nullptr, NH,     W6, b6, bufA, NH);
    gemm_kernel<false><<<dim3(MT, 3), blk>>>(bufA, NH,  nullptr, NH,     Wo, bo, out,  NF);

    finalize_kernel<<<1, blk>>>(out);
}

// round 2
// speedup vs baseline: 1.0089x; 1.0089x over previous
#include <cuda_runtime.h>
#include <math.h>

#define NB 131072
#define NH 512
#define NL 256
#define NK 1024
#define NF 267

// ---------------- scratch (device globals: allocation-free) ----------------
__device__ float  g_bufA[(size_t)NB * NH];
__device__ float  g_bufB[(size_t)NB * NH];
__device__ float  g_mu  [(size_t)NB * NL];
__device__ float  g_q   [(size_t)NB * NL];
__device__ float  g_enorm[NK];
__device__ int    g_counts[NK];
__device__ double g_loss;

// ---------------- generic fused GEMM: C = act( [A0|A1] @ W + bias ) --------
// A logical shape [NB, Ktot], A0 width K0, A1 width Ktot-K0 (A1 may be null
// when K0 == Ktot). W is [Ktot, N] row-major. Tile: 128x128x16, 256 threads,
// 8x8 per-thread micro-tile.
template <bool RELU>
__global__ void __launch_bounds__(256, 2) gemm_kernel(
    const float* __restrict__ A0, int K0,
    const float* __restrict__ A1, int Ktot,
    const float* __restrict__ W, const float* __restrict__ bias,
    float* __restrict__ C, int N)
{
    __shared__ float As[128][17];   // [m][k], padded: conflict-free store & read
    __shared__ float Ws[16][128];   // [k][n]

    const int t  = threadIdx.x;
    const int tx = t & 15;
    const int ty = t >> 4;
    const int m0 = blockIdx.x * 128;
    const int n0 = blockIdx.y * 128;
    const int K1 = Ktot - K0;

    float acc[8][8];
#pragma unroll
    for (int i = 0; i < 8; ++i)
#pragma unroll
        for (int j = 0; j < 8; ++j) acc[i][j] = 0.f;

    const int nKt = (Ktot + 15) >> 4;
    for (int kt = 0; kt < nKt; ++kt) {
        // A tile: 2048 elems, 8 per thread, coalesced along k
#pragma unroll
        for (int i = 0; i < 8; ++i) {
            int li = t + i * 256;
            int m = li >> 4, k = li & 15;
            int kg = kt * 16 + k;
            float v = 0.f;
            if (kg < Ktot) {
                size_t row = (size_t)(m0 + m);
                v = (kg < K0) ? A0[row * K0 + kg]
                              : A1[row * K1 + (kg - K0)];
            }
            As[m][k] = v;
        }
        // W tile: coalesced along n
#pragma unroll
        for (int i = 0; i < 8; ++i) {
            int li = t + i * 256;
            int n = li & 127, k = li >> 7;
            int kg = kt * 16 + k;
            int ng = n0 + n;
            float v = 0.f;
            if (kg < Ktot && ng < N) v = W[(size_t)kg * N + ng];
            Ws[k][n] = v;
        }
        __syncthreads();
#pragma unroll
        for (int kk = 0; kk < 16; ++kk) {
            float a[8], b[8];
#pragma unroll
            for (int i = 0; i < 8; ++i) a[i] = As[ty * 8 + i][kk];
            float4 b0 = *(const float4*)&Ws[kk][tx * 8];
            float4 b1 = *(const float4*)&Ws[kk][tx * 8 + 4];
            b[0] = b0.x; b[1] = b0.y; b[2] = b0.z; b[3] = b0.w;
            b[4] = b1.x; b[5] = b1.y; b[6] = b1.z; b[7] = b1.w;
#pragma unroll
            for (int i = 0; i < 8; ++i)
#pragma unroll
                for (int j = 0; j < 8; ++j) acc[i][j] += a[i] * b[j];
        }
        __syncthreads();
    }

    // epilogue: bias + optional relu
    if ((n0 + 128 <= N) && ((N & 3) == 0)) {
#pragma unroll
        for (int i = 0; i < 8; ++i) {
            size_t row = (size_t)(m0 + ty * 8 + i);
            float* cp = &C[row * N + n0 + tx * 8];
            float o[8];
#pragma unroll
            for (int j = 0; j < 8; ++j) {
                float v = acc[i][j] + bias[n0 + tx * 8 + j];
                if (RELU) v = fmaxf(v, 0.f);
                o[j] = v;
            }
            *(float4*)cp       = make_float4(o[0], o[1], o[2], o[3]);
            *(float4*)(cp + 4) = make_float4(o[4], o[5], o[6], o[7]);
        }
    } else {
#pragma unroll
        for (int j = 0; j < 8; ++j) {
            int ng = n0 + tx * 8 + j;
            if (ng >= N) continue;
            float bb = bias[ng];
#pragma unroll
            for (int i = 0; i < 8; ++i) {
                float v = acc[i][j] + bb;
                if (RELU) v = fmaxf(v, 0.f);
                C[(size_t)(m0 + ty * 8 + i) * N + ng] = v;
            }
        }
    }
}

// ---------------- precompute ||e_k||^2 ----------------
__global__ void enorm_kernel(const float* __restrict__ embed)
{
    int k = blockIdx.x * 256 + threadIdx.x;  // 1024 total
    float s = 0.f;
    for (int l = 0; l < NL; ++l) {
        float v = embed[(size_t)l * NK + k];
        s += v * v;
    }
    g_enorm[k] = s;
}

__global__ void zero_kernel()
{
    int t = blockIdx.x * 256 + threadIdx.x;
    if (t < NK) g_counts[t] = 0;
    if (t == 0) g_loss = 0.0;
}

// ---------------- vector quantizer ----------------
// Per 128-row tile: scores[k] = ||e_k||^2 - 2 mu.e_k (row-constant ||mu||^2
// dropped; argmin unchanged). GEMM skeleton, per-row argmin, gather quantize,
// MSE partial sum, code histogram.
__global__ void __launch_bounds__(256) vq_kernel(
    const float* __restrict__ mu, const float* __restrict__ embed,
    float* __restrict__ quant)
{
    __shared__ float As[128][17];
    __shared__ float Es[16][128];
    __shared__ float redv[128][17];
    __shared__ int   redi[128][17];
    __shared__ int   sidx[128];
    __shared__ float rsum[256];

    const int t  = threadIdx.x;
    const int tx = t & 15;
    const int ty = t >> 4;
    const int m0 = blockIdx.x * 128;

    float best[8]; int bidx[8];
#pragma unroll
    for (int i = 0; i < 8; ++i) { best[i] = 3.4e38f; bidx[i] = 0; }

    for (int nt = 0; nt < 8; ++nt) {        // 8 code tiles of 128
        float acc[8][8];
#pragma unroll
        for (int i = 0; i < 8; ++i)
#pragma unroll
            for (int j = 0; j < 8; ++j) acc[i][j] = 0.f;

        for (int kt = 0; kt < 16; ++kt) {   // K = 256
#pragma unroll
            for (int i = 0; i < 8; ++i) {
                int li = t + i * 256;
                int m = li >> 4, k = li & 15;
                As[m][k] = mu[(size_t)(m0 + m) * NL + kt * 16 + k];
            }
#pragma unroll
            for (int i = 0; i < 8; ++i) {
                int li = t + i * 256;
                int n = li & 127, k = li >> 7;
                Es[k][n] = embed[(size_t)(kt * 16 + k) * NK + nt * 128 + n];
            }
            __syncthreads();
#pragma unroll
            for (int kk = 0; kk < 16; ++kk) {
                float a[8], b[8];
#pragma unroll
                for (int i = 0; i < 8; ++i) a[i] = As[ty * 8 + i][kk];
                float4 b0 = *(const float4*)&Es[kk][tx * 8];
                float4 b1 = *(const float4*)&Es[kk][tx * 8 + 4];
                b[0] = b0.x; b[1] = b0.y; b[2] = b0.z; b[3] = b0.w;
                b[4] = b1.x; b[5] = b1.y; b[6] = b1.z; b[7] = b1.w;
#pragma unroll
                for (int i = 0; i < 8; ++i)
#pragma unroll
                    for (int j = 0; j < 8; ++j) acc[i][j] += a[i] * b[j];
            }
            __syncthreads();
        }
#pragma unroll
        for (int j = 0; j < 8; ++j) {
            int code = nt * 128 + tx * 8 + j;
            float en = g_enorm[code];
#pragma unroll
            for (int i = 0; i < 8; ++i) {
                float d = en - 2.f * acc[i][j];
                if (d < best[i] || (d == best[i] && code < bidx[i])) {
                    best[i] = d; bidx[i] = code;
                }
            }
        }
    }

    // cross-thread argmin per row (tie -> smallest code, matches argmax(-d))
#pragma unroll
    for (int i = 0; i < 8; ++i) {
        redv[ty * 8 + i][tx] = best[i];
        redi[ty * 8 + i][tx] = bidx[i];
    }
    __syncthreads();
    if (t < 128) {
        float bv = redv[t][0]; int bi = redi[t][0];
#pragma unroll
        for (int x = 1; x < 16; ++x) {
            float v = redv[t][x]; int ix = redi[t][x];
            if (v < bv || (v == bv && ix < bi)) { bv = v; bi = ix; }
        }
        sidx[t] = bi;
        atomicAdd(&g_counts[bi], 1);
    }
    __syncthreads();

    // gather quantize rows (embed fully L2-resident) + MSE partial
    float ls = 0.f;
    for (int r = 0; r < 128; ++r) {
        int code = sidx[r];
        float qv = embed[(size_t)t * NK + code];          // t = latent dim (0..255)
        float mv = mu[(size_t)(m0 + r) * NL + t];
        quant[(size_t)(m0 + r) * NL + t] = qv;
        float d = qv - mv;
        ls += d * d;
    }
    rsum[t] = ls;
    __syncthreads();
    for (int s = 128; s > 0; s >>= 1) {
        if (t < s) rsum[t] += rsum[t + s];
        __syncthreads();
    }
    if (t == 0) atomicAdd(&g_loss, (double)rsum[0]);
}

// ---------------- loss / perplexity scalars ----------------
__global__ void finalize_kernel(float* __restrict__ out)
{
    __shared__ double sh[256];
    int t = threadIdx.x;
    double e = 0.0;
    for (int k = t; k < NK; k += 256) {
        double p = (double)g_counts[k] / (double)NB;
        e += p * log(p + 1e-10);
    }
    sh[t] = e;
    __syncthreads();
    for (int s = 128; s > 0; s >>= 1) {
        if (t < s) sh[t] += sh[t + s];
        __syncthreads();
    }
    if (t == 0) {
        out[(size_t)NB * NF]     = (float)(g_loss / ((double)NB * (double)NL));
        out[(size_t)NB * NF + 1] = (float)exp(-sh[0]);
    }
}

// ---------------- launch ----------------
extern "C" void kernel_launch(void* const* d_in, const int* in_sizes, int n_in,
                              void* d_out, int out_size)
{
    const float* x     = (const float*)d_in[0];
    const float* c     = (const float*)d_in[1];
    const float* W1    = (const float*)d_in[2];
    const float* b1    = (const float*)d_in[3];
    const float* W2    = (const float*)d_in[4];
    const float* b2    = (const float*)d_in[5];
    const float* W3    = (const float*)d_in[6];
    const float* b3    = (const float*)d_in[7];
    const float* Wmu   = (const float*)d_in[8];
    const float* bmu   = (const float*)d_in[9];
    const float* W4    = (const float*)d_in[10];
    const float* b4    = (const float*)d_in[11];
    const float* W5    = (const float*)d_in[12];
    const float* b5    = (const float*)d_in[13];
    const float* W6    = (const float*)d_in[14];
    const float* b6    = (const float*)d_in[15];
    const float* Wo    = (const float*)d_in[16];
    const float* bo    = (const float*)d_in[17];
    const float* embed = (const float*)d_in[18];
    float* out = (float*)d_out;

    float *bufA, *bufB, *mu, *q;
    cudaGetSymbolAddress((void**)&bufA, g_bufA);
    cudaGetSymbolAddress((void**)&bufB, g_bufB);
    cudaGetSymbolAddress((void**)&mu,   g_mu);
    cudaGetSymbolAddress((void**)&q,    g_q);

    const dim3 blk(256);
    const int MT = NB / 128;  // 1024

    zero_kernel<<<4, blk>>>();
    enorm_kernel<<<4, blk>>>(embed);

    // encoder
    gemm_kernel<true ><<<dim3(MT, 4), blk>>>(x,    NF,  c,      2 * NF, W1,  b1,  bufA, NH);
    gemm_kernel<true ><<<dim3(MT, 4), blk>>>(bufA, NH,  nullptr, NH,    W2,  b2,  bufB, NH);
    gemm_kernel<true ><<<dim3(MT, 4), blk>>>(bufB, NH,  nullptr, NH,    W3,  b3,  bufA, NH);
    gemm_kernel<false><<<dim3(MT, 2), blk>>>(bufA, NH,  nullptr, NH,    Wmu, bmu, mu,   NL);

    // vector quantizer
    vq_kernel<<<MT, blk>>>(mu, embed, q);

    // decoder
    gemm_kernel<true ><<<dim3(MT, 4), blk>>>(q,    NL,  c,      NL + NF, W4, b4, bufA, NH);
    gemm_kernel<true ><<<dim3(MT, 4), blk>>>(bufA, NH,  nullptr, NH,     W5, b5, bufB, NH);
    gemm_kernel<true ><<<dim3(MT, 4), blk>>>(bufB, NH,  nullptr, NH,     W6, b6, bufA, NH);
    gemm_kernel<false><<<dim3(MT, 3), blk>>>(bufA, NH,  nullptr, NH,     Wo, bo, out,  NF);

    finalize_kernel<<<1, blk>>>(out);
}

// round 4
// speedup vs baseline: 1.7221x; 1.7068x over previous
#include <cuda_runtime.h>
#include <math.h>
#include <stdint.h>

#define NB 131072
#define NH 512
#define NL 256
#define NKC 1024
#define NF 267
#define NTILE 256
#define KTILE 32
#define TILE_F (KTILE * 256)
#define SMEM_BYTES (2 * 2 * TILE_F * 4)   // As[2][..] + Ws[2][..] = 128 KB

typedef unsigned long long u64;

__device__ float  g_bufA[(size_t)NB * NH];
__device__ float  g_bufB[(size_t)NB * NH];
__device__ float  g_mu[(size_t)NB * NL];
__device__ float  g_q[(size_t)NB * NL];
__device__ float  g_enorm[NKC];
__device__ u64    g_key[NB];
__device__ int    g_counts[NKC];
__device__ double g_loss;

#define FFMA2(d, a, b) asm("fma.rn.f32x2 %0, %1, %2, %0;" : "+l"(d) : "l"(a), "l"(b))
__device__ __forceinline__ u64 dupf(float v) {
    u64 r; asm("mov.b64 %0, {%1, %1};" : "=l"(r) : "f"(v)); return r;
}
__device__ __forceinline__ float lof(u64 v) { return __uint_as_float((unsigned)v); }
__device__ __forceinline__ float hif(u64 v) { return __uint_as_float((unsigned)(v >> 32)); }

// ---------------------------------------------------------------------------
// MODE 0: relu store, 1: linear store, 2: VQ argmin (bias = ||e||^2, keys out)
// C = act( [A0|A1] @ W + bias ), W row-major [Ktot x N]
// ---------------------------------------------------------------------------
template <int MODE>
__global__ void __launch_bounds__(256, 1) gemm2(
    const float* __restrict__ A0, int K0,
    const float* __restrict__ A1, int Ktot,
    const float* __restrict__ W, const float* __restrict__ bias,
    float* __restrict__ C, int N, u64* __restrict__ keys)
{
    extern __shared__ float dyn[];
    float* As = dyn;               // [2][KTILE][256]  (128 m, duplicated pairs)
    float* Ws = dyn + 2 * TILE_F;  // [2][KTILE][256]

    const int tid = threadIdx.x;
    const int tx = tid & 15, ty = tid >> 4;
    const int m0 = blockIdx.x * 128, n0 = blockIdx.y * NTILE;
    const int K1 = Ktot - K0;
    const bool wAligned = ((N & 3) == 0);
    const int am = tid >> 1;             // A-load row
    const int ak = (tid & 1) * 16;       // A-load k offset
    const int nT = (Ktot + KTILE - 1) / KTILE;

    u64 acc[8][8];
#pragma unroll
    for (int i = 0; i < 8; ++i)
#pragma unroll
        for (int j = 0; j < 8; ++j) acc[i][j] = 0ull;

    float  aReg[16];
    float4 bReg[8];

#define LOADA(kt) do {                                                        \
    _Pragma("unroll")                                                         \
    for (int q = 0; q < 16; ++q) {                                            \
        int k = (kt) * KTILE + ak + q;                                        \
        float v = 0.f;                                                        \
        if (k < K0)        v = A0[(size_t)(m0 + am) * K0 + k];                \
        else if (k < Ktot) v = A1[(size_t)(m0 + am) * K1 + (k - K0)];         \
        aReg[q] = v;                                                          \
    } } while (0)

#define LOADB(kt) do {                                                        \
    _Pragma("unroll")                                                         \
    for (int i = 0; i < 8; ++i) {                                             \
        int idx = tid + i * 256;                                              \
        int k = idx >> 6, n4 = (idx & 63) * 4;                                \
        int kg = (kt) * KTILE + k;                                            \
        int ng = n0 + n4;                                                     \
        float4 v = make_float4(0.f, 0.f, 0.f, 0.f);                           \
        if (kg < Ktot) {                                                      \
            if (wAligned) {                                                   \
                if (ng < N) v = *(const float4*)&W[(size_t)kg * N + ng];      \
            } else {                                                          \
                const float* wp = &W[(size_t)kg * N];                         \
                if (ng + 0 < N) v.x = wp[ng + 0];                             \
                if (ng + 1 < N) v.y = wp[ng + 1];                             \
                if (ng + 2 < N) v.z = wp[ng + 2];                             \
                if (ng + 3 < N) v.w = wp[ng + 3];                             \
            }                                                                 \
        }                                                                     \
        bReg[i] = v;                                                          \
    } } while (0)

#define STST(p) do {                                                          \
    float* ab = As + (p) * TILE_F;                                            \
    _Pragma("unroll")                                                         \
    for (int q = 0; q < 16; ++q)                                              \
        *(u64*)(ab + (ak + q) * 256 + 2 * am) = dupf(aReg[q]);                \
    float* wb = Ws + (p) * TILE_F;                                            \
    _Pragma("unroll")                                                         \
    for (int i = 0; i < 8; ++i) {                                             \
        int idx = tid + i * 256;                                              \
        *(float4*)(wb + (idx >> 6) * 256 + (idx & 63) * 4) = bReg[i];         \
    } } while (0)

    LOADA(0); LOADB(0);
    STST(0);
    __syncthreads();

    for (int kt = 0; kt < nT; ++kt) {
        const int p = kt & 1;
        if (kt + 1 < nT) { LOADA(kt + 1); LOADB(kt + 1); }

        const float* ab = As + p * TILE_F + ty * 16;
        const float* wb = Ws + p * TILE_F + tx * 4;
#pragma unroll 4
        for (int k = 0; k < KTILE; ++k) {
            u64 a[8], b[8];
            const ulonglong2* ap = (const ulonglong2*)(ab + k * 256);
#pragma unroll
            for (int q = 0; q < 4; ++q) { ulonglong2 t = ap[q]; a[2*q] = t.x; a[2*q+1] = t.y; }
#pragma unroll
            for (int q = 0; q < 4; ++q) {
                ulonglong2 t = *(const ulonglong2*)(wb + k * 256 + q * 64);
                b[2*q] = t.x; b[2*q+1] = t.y;
            }
#pragma unroll
            for (int i = 0; i < 8; ++i)
#pragma unroll
                for (int j = 0; j < 8; ++j) FFMA2(acc[i][j], a[i], b[j]);
        }
        if (kt + 1 < nT) STST((kt + 1) & 1);
        __syncthreads();
    }

    if (MODE == 2) {
        // cols for acc[i][j]: n0 + (j>>1)*64 + tx*4 + (j&1)*2 + {0,1}
        u64* red = (u64*)dyn;   // [128][17]
#pragma unroll
        for (int i = 0; i < 8; ++i) {
            u64 best = ~0ull;
#pragma unroll
            for (int j = 0; j < 8; ++j) {
                int c0 = n0 + (j >> 1) * 64 + tx * 4 + (j & 1) * 2;
                float d0 = bias[c0]     - 2.f * lof(acc[i][j]);
                float d1 = bias[c0 + 1] - 2.f * hif(acc[i][j]);
                unsigned u0 = __float_as_uint(d0);
                u0 = (u0 & 0x80000000u) ? ~u0 : (u0 | 0x80000000u);
                unsigned u1 = __float_as_uint(d1);
                u1 = (u1 & 0x80000000u) ? ~u1 : (u1 | 0x80000000u);
                u64 k0 = ((u64)u0 << 32) | (unsigned)c0;
                u64 k1 = ((u64)u1 << 32) | (unsigned)(c0 + 1);
                if (k0 < best) best = k0;
                if (k1 < best) best = k1;
            }
            red[(ty * 8 + i) * 17 + tx] = best;
        }
        __syncthreads();
        if (tid < 128) {
            u64 b = red[tid * 17];
#pragma unroll
            for (int x = 1; x < 16; ++x) { u64 v = red[tid * 17 + x]; if (v < b) b = v; }
            atomicMin(&keys[m0 + tid], b);
        }
        return;
    }

    if (wAligned && n0 + NTILE <= N) {
#pragma unroll
        for (int i = 0; i < 8; ++i) {
            size_t row = (size_t)(m0 + ty * 8 + i);
#pragma unroll
            for (int q = 0; q < 4; ++q) {
                int cb = n0 + q * 64 + tx * 4;
                float4 o;
                o.x = lof(acc[i][2*q])   + bias[cb + 0];
                o.y = hif(acc[i][2*q])   + bias[cb + 1];
                o.z = lof(acc[i][2*q+1]) + bias[cb + 2];
                o.w = hif(acc[i][2*q+1]) + bias[cb + 3];
                if (MODE == 0) {
                    o.x = fmaxf(o.x, 0.f); o.y = fmaxf(o.y, 0.f);
                    o.z = fmaxf(o.z, 0.f); o.w = fmaxf(o.w, 0.f);
                }
                *(float4*)(C + row * N + cb) = o;
            }
        }
    } else {
#pragma unroll
        for (int i = 0; i < 8; ++i) {
            size_t row = (size_t)(m0 + ty * 8 + i);
#pragma unroll
            for (int j = 0; j < 8; ++j) {
                int c0 = n0 + (j >> 1) * 64 + tx * 4 + (j & 1) * 2;
                if (c0 < N) {
                    float v = lof(acc[i][j]) + bias[c0];
                    if (MODE == 0) v = fmaxf(v, 0.f);
                    C[row * N + c0] = v;
                }
                if (c0 + 1 < N) {
                    float v = hif(acc[i][j]) + bias[c0 + 1];
                    if (MODE == 0) v = fmaxf(v, 0.f);
                    C[row * N + c0 + 1] = v;
                }
            }
        }
    }
#undef LOADA
#undef LOADB
#undef STST
}

// ---------------------------------------------------------------------------
__global__ void init_kernel() {
    int t = blockIdx.x * 256 + threadIdx.x;
    if (t < NB) g_key[t] = ~0ull;
    if (t < NKC) g_counts[t] = 0;
    if (t == 0) g_loss = 0.0;
}
__global__ void enorm_kernel(const float* __restrict__ e) {
    int k = blockIdx.x * 256 + threadIdx.x;
    float s = 0.f;
    for (int l = 0; l < NL; ++l) { float v = e[(size_t)l * NKC + k]; s += v * v; }
    g_enorm[k] = s;
}
__global__ void vq_gather_kernel(const float* __restrict__ mu,
                                 const float* __restrict__ embed,
                                 float* __restrict__ q) {
    __shared__ float s_ls[8];
    const int wid = threadIdx.x >> 5, lane = threadIdx.x & 31;
    const size_t row = (size_t)blockIdx.x * 8 + wid;
    const int ind = (int)(g_key[row] & 0xFFFFFFFFull);
    if (lane == 0) atomicAdd(&g_counts[ind], 1);
    float ls = 0.f;
#pragma unroll
    for (int i = 0; i < 8; ++i) {
        int dim = i * 32 + lane;
        float qv = embed[(size_t)dim * NKC + ind];
        float d = qv - mu[row * NL + dim];
        q[row * NL + dim] = qv;
        ls += d * d;
    }
#pragma unroll
    for (int s = 16; s > 0; s >>= 1) ls += __shfl_down_sync(0xFFFFFFFF, ls, s);
    if (lane == 0) s_ls[wid] = ls;
    __syncthreads();
    if (threadIdx.x == 0) {
        double t = 0.0;
        for (int w = 0; w < 8; ++w) t += (double)s_ls[w];
        atomicAdd(&g_loss, t);
    }
}
__global__ void finalize_kernel(float* __restrict__ out) {
    __shared__ double sh[256];
    int t = threadIdx.x;
    double e = 0.0;
    for (int k = t; k < NKC; k += 256) {
        double p = (double)g_counts[k] / (double)NB;
        e += p * log(p + 1e-10);
    }
    sh[t] = e;
    __syncthreads();
    for (int s = 128; s > 0; s >>= 1) { if (t < s) sh[t] += sh[t + s]; __syncthreads(); }
    if (t == 0) {
        out[(size_t)NB * NF]     = (float)(g_loss / ((double)NB * (double)NL));
        out[(size_t)NB * NF + 1] = (float)exp(-sh[0]);
    }
}

// ---------------------------------------------------------------------------
extern "C" void kernel_launch(void* const* d_in, const int* in_sizes, int n_in,
                              void* d_out, int out_size)
{
    const float* x     = (const float*)d_in[0];
    const float* c     = (const float*)d_in[1];
    const float* W1    = (const float*)d_in[2];
    const float* b1    = (const float*)d_in[3];
    const float* W2    = (const float*)d_in[4];
    const float* b2    = (const float*)d_in[5];
    const float* W3    = (const float*)d_in[6];
    const float* b3    = (const float*)d_in[7];
    const float* Wmu   = (const float*)d_in[8];
    const float* bmu   = (const float*)d_in[9];
    const float* W4    = (const float*)d_in[10];
    const float* b4    = (const float*)d_in[11];
    const float* W5    = (const float*)d_in[12];
    const float* b5    = (const float*)d_in[13];
    const float* W6    = (const float*)d_in[14];
    const float* b6    = (const float*)d_in[15];
    const float* Wo    = (const float*)d_in[16];
    const float* bo    = (const float*)d_in[17];
    const float* embed = (const float*)d_in[18];
    float* out = (float*)d_out;

    float *bufA, *bufB, *mu, *q, *en;
    u64* keys;
    cudaGetSymbolAddress((void**)&bufA, g_bufA);
    cudaGetSymbolAddress((void**)&bufB, g_bufB);
    cudaGetSymbolAddress((void**)&mu,   g_mu);
    cudaGetSymbolAddress((void**)&q,    g_q);
    cudaGetSymbolAddress((void**)&en,   g_enorm);
    cudaGetSymbolAddress((void**)&keys, g_key);

    cudaFuncSetAttribute(gemm2<0>, cudaFuncAttributeMaxDynamicSharedMemorySize, SMEM_BYTES);
    cudaFuncSetAttribute(gemm2<1>, cudaFuncAttributeMaxDynamicSharedMemorySize, SMEM_BYTES);
    cudaFuncSetAttribute(gemm2<2>, cudaFuncAttributeMaxDynamicSharedMemorySize, SMEM_BYTES);

    const int MT = NB / 128;  // 1024
    init_kernel<<<512, 256>>>();
    enorm_kernel<<<4, 256>>>(embed);

    // encoder
    gemm2<0><<<dim3(MT, 2), 256, SMEM_BYTES>>>(x,    NF, c,       2 * NF, W1,  b1,  bufA, NH, 0);
    gemm2<0><<<dim3(MT, 2), 256, SMEM_BYTES>>>(bufA, NH, nullptr, NH,     W2,  b2,  bufB, NH, 0);
    gemm2<0><<<dim3(MT, 2), 256, SMEM_BYTES>>>(bufB, NH, nullptr, NH,     W3,  b3,  bufA, NH, 0);
    gemm2<1><<<dim3(MT, 1), 256, SMEM_BYTES>>>(bufA, NH, nullptr, NH,     Wmu, bmu, mu,   NL, 0);
    // VQ: scores = ||e||^2 - 2 mu.e over 1024 codes (argmin keys)
    gemm2<2><<<dim3(MT, 4), 256, SMEM_BYTES>>>(mu, NL, nullptr, NL, embed, en, nullptr, NKC, keys);
    vq_gather_kernel<<<NB / 8, 256>>>(mu, embed, q);
    // decoder
    gemm2<0><<<dim3(MT, 2), 256, SMEM_BYTES>>>(q,    NL, c,       NL + NF, W4, b4, bufA, NH, 0);
    gemm2<0><<<dim3(MT, 2), 256, SMEM_BYTES>>>(bufA, NH, nullptr, NH,      W5, b5, bufB, NH, 0);
    gemm2<0><<<dim3(MT, 2), 256, SMEM_BYTES>>>(bufB, NH, nullptr, NH,      W6, b6, bufA, NH, 0);
    gemm2<1><<<dim3(MT, 2), 256, SMEM_BYTES>>>(bufA, NH, nullptr, NH,      Wo, bo, out,  NF, 0);
    finalize_kernel<<<1, 256>>>(out);
}